// round 10
// baseline (speedup 1.0000x reference)
#include <cuda_runtime.h>
#include <cuda_bf16.h>

#define EPS 1e-6f
#define ITERS 20

typedef unsigned long long u64;

__device__ __forceinline__ float frcp(float x) {
    float y;
    asm("rcp.approx.ftz.f32 %0, %1;" : "=f"(y) : "f"(x));
    return y;
}
__device__ __forceinline__ u64 pack2(float lo, float hi) {
    u64 r;
    asm("mov.b64 %0, {%1, %2};" : "=l"(r) : "f"(lo), "f"(hi));
    return r;
}
__device__ __forceinline__ void unpack2(u64 v, float& lo, float& hi) {
    asm("mov.b64 {%0, %1}, %2;" : "=f"(lo), "=f"(hi) : "l"(v));
}
__device__ __forceinline__ u64 mul2(u64 a, u64 b) {
    u64 d;
    asm("mul.rn.f32x2 %0, %1, %2;" : "=l"(d) : "l"(a), "l"(b));
    return d;
}
__device__ __forceinline__ u64 add2(u64 a, u64 b) {
    u64 d;
    asm("add.rn.f32x2 %0, %1, %2;" : "=l"(d) : "l"(a), "l"(b));
    return d;
}
__device__ __forceinline__ u64 fma2(u64 a, u64 b, u64 c) {
    u64 d;
    asm("fma.rn.f32x2 %0, %1, %2, %3;" : "=l"(d) : "l"(a), "l"(b), "l"(c));
    return d;
}

// Batched 4-way reciprocal on token-packed lanes:
// R[k] = 1/S[k] elementwise (each u64 = 2 tokens), using ONE scalar rcp per token.
__device__ __forceinline__ void brcp4v(const u64 S0, const u64 S1,
                                       const u64 S2, const u64 S3,
                                       u64& R0, u64& R1, u64& R2, u64& R3) {
    u64 u = mul2(S0, S1);
    u64 v = mul2(S2, S3);
    u64 w = mul2(u, v);
    float wl, wh;
    unpack2(w, wl, wh);
    u64 q = pack2(frcp(wl), frcp(wh));
    u64 a = mul2(q, v);   // 1/(S0*S1) per lane
    u64 b = mul2(q, u);   // 1/(S2*S3) per lane
    R0 = mul2(a, S1);
    R1 = mul2(a, S0);
    R2 = mul2(b, S3);
    R3 = mul2(b, S2);
}

// Per-token prologue: load 24 features, compute+store pre/post, produce softmax+EPS matrix m.
__device__ __forceinline__ void token_prologue(
    const float* __restrict__ mixes, int t, bool do_store,
    float4* op, float4* oq,
    float s0, float s1, float s2, const float* sb,
    float m[4][4])
{
    const float4* mp = (const float4*)(mixes + (size_t)t * 24);
    float4 v0 = __ldcs(mp + 0);
    float4 v1 = __ldcs(mp + 1);
    float4 v2 = __ldcs(mp + 2);
    float4 v3 = __ldcs(mp + 3);
    float4 v4 = __ldcs(mp + 4);
    float4 v5 = __ldcs(mp + 5);

    {
        float p[4] = {v0.x, v0.y, v0.z, v0.w};
        #pragma unroll
        for (int i = 0; i < 4; i++)
            p[i] = frcp(1.0f + __expf(-fmaf(p[i], s0, sb[i]))) + EPS;
        if (do_store) __stcs(op + t, make_float4(p[0], p[1], p[2], p[3]));
    }
    {
        float p[4] = {v1.x, v1.y, v1.z, v1.w};
        #pragma unroll
        for (int i = 0; i < 4; i++)
            p[i] = 2.0f * frcp(1.0f + __expf(-fmaf(p[i], s1, sb[4 + i])));
        if (do_store) __stcs(oq + t, make_float4(p[0], p[1], p[2], p[3]));
    }

    float mm[4][4] = {
        {v2.x, v2.y, v2.z, v2.w},
        {v3.x, v3.y, v3.z, v3.w},
        {v4.x, v4.y, v4.z, v4.w},
        {v5.x, v5.y, v5.z, v5.w},
    };
    #pragma unroll
    for (int i = 0; i < 4; i++) {
        #pragma unroll
        for (int j = 0; j < 4; j++)
            mm[i][j] = __expf(fmaf(mm[i][j], s2, sb[8 + i * 4 + j]));
        float inv = frcp((mm[i][0] + mm[i][1]) + (mm[i][2] + mm[i][3]));
        #pragma unroll
        for (int j = 0; j < 4; j++)
            m[i][j] = fmaf(mm[i][j], inv, EPS);   // softmax + EPS
    }
}

__global__ __launch_bounds__(256)
void hc_sinkhorn_kernel(const float* __restrict__ mixes,
                        const float* __restrict__ hc_scale,
                        const float* __restrict__ hc_base,
                        float* __restrict__ out,
                        int n_tok, int n_half)
{
    __shared__ float sb[24];
    __shared__ float ss[3];
    if (threadIdx.x < 24) sb[threadIdx.x] = hc_base[threadIdx.x];
    if (threadIdx.x < 3)  ss[threadIdx.x] = hc_scale[threadIdx.x];
    __syncthreads();

    const int t = blockIdx.x * blockDim.x + threadIdx.x;
    if (t >= n_half) return;

    const int ta = t;
    const int tb = t + n_half;
    const bool vb = (tb < n_tok);
    const int tbe = vb ? tb : ta;   // dummy-compute ta's data if odd tail

    const float s0 = ss[0], s1 = ss[1], s2 = ss[2];
    float4* op = (float4*)out;
    float4* oq = (float4*)(out + (size_t)n_tok * 4);
    float4* oc = (float4*)(out + (size_t)n_tok * 8);

    float ma[4][4], mb[4][4];
    token_prologue(mixes, ta, true, op, oq, s0, s1, s2, sb, ma);
    token_prologue(mixes, tbe, vb, op, oq, s0, s1, s2, sb, mb);

    // Pack across tokens: lane0 = token A, lane1 = token B. ONE layout for both passes.
    u64 M[4][4];
    #pragma unroll
    for (int i = 0; i < 4; i++)
        #pragma unroll
        for (int j = 0; j < 4; j++)
            M[i][j] = pack2(ma[i][j], mb[i][j]);

    // ---- Sinkhorn: N_ij = M_ij * r_i * c_j ----
    u64 r0, r1, r2, r3, c0, c1, c2, c3;

    // Initial col-normalize (r = 1): c_j = 1/colsum_j
    {
        u64 S0 = add2(add2(M[0][0], M[1][0]), add2(M[2][0], M[3][0]));
        u64 S1 = add2(add2(M[0][1], M[1][1]), add2(M[2][1], M[3][1]));
        u64 S2 = add2(add2(M[0][2], M[1][2]), add2(M[2][2], M[3][2]));
        u64 S3 = add2(add2(M[0][3], M[1][3]), add2(M[2][3], M[3][3]));
        brcp4v(S0, S1, S2, S3, c0, c1, c2, c3);
    }

    #pragma unroll 1
    for (int it = 0; it < ITERS - 1; it++) {
        // Row pass: T_i = sum_j M[i][j]*c_j ; r_i = 1/T_i
        u64 T0 = mul2(M[0][0], c0);
        u64 T1 = mul2(M[1][0], c0);
        u64 T2 = mul2(M[2][0], c0);
        u64 T3 = mul2(M[3][0], c0);
        T0 = fma2(M[0][1], c1, T0);
        T1 = fma2(M[1][1], c1, T1);
        T2 = fma2(M[2][1], c1, T2);
        T3 = fma2(M[3][1], c1, T3);
        T0 = fma2(M[0][2], c2, T0);
        T1 = fma2(M[1][2], c2, T1);
        T2 = fma2(M[2][2], c2, T2);
        T3 = fma2(M[3][2], c2, T3);
        T0 = fma2(M[0][3], c3, T0);
        T1 = fma2(M[1][3], c3, T1);
        T2 = fma2(M[2][3], c3, T2);
        T3 = fma2(M[3][3], c3, T3);
        brcp4v(T0, T1, T2, T3, r0, r1, r2, r3);

        // Col pass: S_j = sum_i M[i][j]*r_i ; c_j = 1/S_j
        u64 S0 = mul2(M[0][0], r0);
        u64 S1 = mul2(M[0][1], r0);
        u64 S2 = mul2(M[0][2], r0);
        u64 S3 = mul2(M[0][3], r0);
        S0 = fma2(M[1][0], r1, S0);
        S1 = fma2(M[1][1], r1, S1);
        S2 = fma2(M[1][2], r1, S2);
        S3 = fma2(M[1][3], r1, S3);
        S0 = fma2(M[2][0], r2, S0);
        S1 = fma2(M[2][1], r2, S1);
        S2 = fma2(M[2][2], r2, S2);
        S3 = fma2(M[2][3], r2, S3);
        S0 = fma2(M[3][0], r3, S0);
        S1 = fma2(M[3][1], r3, S1);
        S2 = fma2(M[3][2], r3, S2);
        S3 = fma2(M[3][3], r3, S3);
        brcp4v(S0, S1, S2, S3, c0, c1, c2, c3);
    }

    // ---- Epilogue: N_ij = M_ij * c_j * r_i, unpack lanes, store both tokens ----
    u64 rr[4] = {r0, r1, r2, r3};
    u64 cc[4] = {c0, c1, c2, c3};
    #pragma unroll
    for (int i = 0; i < 4; i++) {
        float a0, a1, a2, a3, b0, b1, b2, b3;
        u64 n0 = mul2(mul2(M[i][0], cc[0]), rr[i]);
        u64 n1 = mul2(mul2(M[i][1], cc[1]), rr[i]);
        u64 n2 = mul2(mul2(M[i][2], cc[2]), rr[i]);
        u64 n3 = mul2(mul2(M[i][3], cc[3]), rr[i]);
        unpack2(n0, a0, b0);
        unpack2(n1, a1, b1);
        unpack2(n2, a2, b2);
        unpack2(n3, a3, b3);
        __stcs(oc + (size_t)ta * 4 + i, make_float4(a0, a1, a2, a3));
        if (vb) __stcs(oc + (size_t)tb * 4 + i, make_float4(b0, b1, b2, b3));
    }
}

extern "C" void kernel_launch(void* const* d_in, const int* in_sizes, int n_in,
                              void* d_out, int out_size)
{
    const float* mixes    = (const float*)d_in[0];
    const float* hc_scale = (const float*)d_in[1];
    const float* hc_base  = (const float*)d_in[2];

    const int n_tok  = in_sizes[0] / 24;
    const int n_half = (n_tok + 1) / 2;
    const int block  = 256;
    const int grid   = (n_half + block - 1) / block;

    hc_sinkhorn_kernel<<<grid, block>>>(mixes, hc_scale, hc_base,
                                        (float*)d_out, n_tok, n_half);
}

// round 12
// speedup vs baseline: 1.0274x; 1.0274x over previous
#include <cuda_runtime.h>
#include <cuda_bf16.h>

#define EPS 1e-6f
#define ITERS 20

typedef unsigned long long u64;

__device__ __forceinline__ float frcp(float x) {
    float y;
    asm("rcp.approx.ftz.f32 %0, %1;" : "=f"(y) : "f"(x));
    return y;
}
__device__ __forceinline__ u64 pack2(float lo, float hi) {
    u64 r;
    asm("mov.b64 %0, {%1, %2};" : "=l"(r) : "f"(lo), "f"(hi));
    return r;
}
__device__ __forceinline__ void unpack2(u64 v, float& lo, float& hi) {
    asm("mov.b64 {%0, %1}, %2;" : "=f"(lo), "=f"(hi) : "l"(v));
}
__device__ __forceinline__ u64 mul2(u64 a, u64 b) {
    u64 d;
    asm("mul.rn.f32x2 %0, %1, %2;" : "=l"(d) : "l"(a), "l"(b));
    return d;
}
__device__ __forceinline__ u64 add2(u64 a, u64 b) {
    u64 d;
    asm("add.rn.f32x2 %0, %1, %2;" : "=l"(d) : "l"(a), "l"(b));
    return d;
}
__device__ __forceinline__ u64 fma2(u64 a, u64 b, u64 c) {
    u64 d;
    asm("fma.rn.f32x2 %0, %1, %2, %3;" : "=l"(d) : "l"(a), "l"(b), "l"(c));
    return d;
}

// Per-lane power-of-two ~1/w: s = 2^{-E(w)-1}, so s*w in [0.5, 1). Pure int ALU.
__device__ __forceinline__ u64 pow2rcp(u64 w) {
    unsigned lo = (unsigned)w;
    unsigned hi = (unsigned)(w >> 32);
    lo = 0x7E800000u - (lo & 0x7F800000u);
    hi = 0x7E800000u - (hi & 0x7F800000u);
    return (u64)lo | ((u64)hi << 32);
}

// Adjugate pass with power-of-2 renormalization:
// r_i = (s*w)/T_i with s*w in [0.5,1). No MUFU, no float pack/unpack.
__device__ __forceinline__ void adjscale(u64 T0, u64 T1, u64 T2, u64 T3,
                                         u64& r0, u64& r1, u64& r2, u64& r3) {
    u64 u = mul2(T0, T1);
    u64 v = mul2(T2, T3);
    u64 w = mul2(u, v);
    u64 s = pow2rcp(w);
    u64 sv = mul2(s, v);
    u64 su = mul2(s, u);
    r0 = mul2(sv, T1);
    r1 = mul2(sv, T0);
    r2 = mul2(su, T3);
    r3 = mul2(su, T2);
}

// Same, but also returns K = s*w (the common normalization constant).
__device__ __forceinline__ void adjscaleK(u64 T0, u64 T1, u64 T2, u64 T3,
                                          u64& r0, u64& r1, u64& r2, u64& r3,
                                          u64& K) {
    u64 u = mul2(T0, T1);
    u64 v = mul2(T2, T3);
    u64 w = mul2(u, v);
    u64 s = pow2rcp(w);
    u64 sv = mul2(s, v);
    u64 su = mul2(s, u);
    K  = mul2(sv, u);   // s*u*v = s*w
    r0 = mul2(sv, T1);
    r1 = mul2(sv, T0);
    r2 = mul2(su, T3);
    r3 = mul2(su, T2);
}

// T_i = sum_j M[i][j] * c_j
__device__ __forceinline__ void matvec_row(const u64 M[4][4],
                                           u64 c0, u64 c1, u64 c2, u64 c3,
                                           u64& T0, u64& T1, u64& T2, u64& T3) {
    T0 = mul2(M[0][0], c0);
    T1 = mul2(M[1][0], c0);
    T2 = mul2(M[2][0], c0);
    T3 = mul2(M[3][0], c0);
    T0 = fma2(M[0][1], c1, T0);
    T1 = fma2(M[1][1], c1, T1);
    T2 = fma2(M[2][1], c1, T2);
    T3 = fma2(M[3][1], c1, T3);
    T0 = fma2(M[0][2], c2, T0);
    T1 = fma2(M[1][2], c2, T1);
    T2 = fma2(M[2][2], c2, T2);
    T3 = fma2(M[3][2], c2, T3);
    T0 = fma2(M[0][3], c3, T0);
    T1 = fma2(M[1][3], c3, T1);
    T2 = fma2(M[2][3], c3, T2);
    T3 = fma2(M[3][3], c3, T3);
}

// S_j = sum_i M[i][j] * r_i
__device__ __forceinline__ void matvec_col(const u64 M[4][4],
                                           u64 r0, u64 r1, u64 r2, u64 r3,
                                           u64& S0, u64& S1, u64& S2, u64& S3) {
    S0 = mul2(M[0][0], r0);
    S1 = mul2(M[0][1], r0);
    S2 = mul2(M[0][2], r0);
    S3 = mul2(M[0][3], r0);
    S0 = fma2(M[1][0], r1, S0);
    S1 = fma2(M[1][1], r1, S1);
    S2 = fma2(M[1][2], r1, S2);
    S3 = fma2(M[1][3], r1, S3);
    S0 = fma2(M[2][0], r2, S0);
    S1 = fma2(M[2][1], r2, S1);
    S2 = fma2(M[2][2], r2, S2);
    S3 = fma2(M[2][3], r2, S3);
    S0 = fma2(M[3][0], r3, S0);
    S1 = fma2(M[3][1], r3, S1);
    S2 = fma2(M[3][2], r3, S2);
    S3 = fma2(M[3][3], r3, S3);
}

// Per-token prologue: load 24 features, compute+store pre/post, produce softmax+EPS matrix.
__device__ __forceinline__ void token_prologue(
    const float* __restrict__ mixes, int t, bool do_store,
    float4* op, float4* oq,
    float s0, float s1, float s2, const float* sb,
    float m[4][4])
{
    const float4* mp = (const float4*)(mixes + (size_t)t * 24);
    float4 v0 = __ldcs(mp + 0);
    float4 v1 = __ldcs(mp + 1);
    float4 v2 = __ldcs(mp + 2);
    float4 v3 = __ldcs(mp + 3);
    float4 v4 = __ldcs(mp + 4);
    float4 v5 = __ldcs(mp + 5);

    {
        float p[4] = {v0.x, v0.y, v0.z, v0.w};
        #pragma unroll
        for (int i = 0; i < 4; i++)
            p[i] = frcp(1.0f + __expf(-fmaf(p[i], s0, sb[i]))) + EPS;
        if (do_store) __stcs(op + t, make_float4(p[0], p[1], p[2], p[3]));
    }
    {
        float p[4] = {v1.x, v1.y, v1.z, v1.w};
        #pragma unroll
        for (int i = 0; i < 4; i++)
            p[i] = 2.0f * frcp(1.0f + __expf(-fmaf(p[i], s1, sb[4 + i])));
        if (do_store) __stcs(oq + t, make_float4(p[0], p[1], p[2], p[3]));
    }

    float mm[4][4] = {
        {v2.x, v2.y, v2.z, v2.w},
        {v3.x, v3.y, v3.z, v3.w},
        {v4.x, v4.y, v4.z, v4.w},
        {v5.x, v5.y, v5.z, v5.w},
    };
    #pragma unroll
    for (int i = 0; i < 4; i++) {
        #pragma unroll
        for (int j = 0; j < 4; j++)
            mm[i][j] = __expf(fmaf(mm[i][j], s2, sb[8 + i * 4 + j]));
        float inv = frcp((mm[i][0] + mm[i][1]) + (mm[i][2] + mm[i][3]));
        #pragma unroll
        for (int j = 0; j < 4; j++)
            m[i][j] = fmaf(mm[i][j], inv, EPS);   // softmax + EPS
    }
}

__global__ __launch_bounds__(256, 3)
void hc_sinkhorn_kernel(const float* __restrict__ mixes,
                        const float* __restrict__ hc_scale,
                        const float* __restrict__ hc_base,
                        float* __restrict__ out,
                        int n_tok, int n_half)
{
    __shared__ float sb[24];
    __shared__ float ss[3];
    if (threadIdx.x < 24) sb[threadIdx.x] = hc_base[threadIdx.x];
    if (threadIdx.x < 3)  ss[threadIdx.x] = hc_scale[threadIdx.x];
    __syncthreads();

    const int t = blockIdx.x * blockDim.x + threadIdx.x;
    if (t >= n_half) return;

    const int ta = t;
    const int tb = t + n_half;
    const bool vb = (tb < n_tok);
    const int tbe = vb ? tb : ta;

    const float s0 = ss[0], s1 = ss[1], s2 = ss[2];
    float4* op = (float4*)out;
    float4* oq = (float4*)(out + (size_t)n_tok * 4);
    float4* oc = (float4*)(out + (size_t)n_tok * 8);

    float ma[4][4], mb[4][4];
    token_prologue(mixes, ta, true, op, oq, s0, s1, s2, sb, ma);
    token_prologue(mixes, tbe, vb, op, oq, s0, s1, s2, sb, mb);

    // Pack across tokens: lane0 = token A, lane1 = token B.
    u64 M[4][4];
    #pragma unroll
    for (int i = 0; i < 4; i++)
        #pragma unroll
        for (int j = 0; j < 4; j++)
            M[i][j] = pack2(ma[i][j], mb[i][j]);

    // ---- Sinkhorn, fully projective: every pass normalizes to K in [0.5,1) ----
    u64 r0, r1, r2, r3, c0, c1, c2, c3;

    // Init col pass (r = 1): colsums then adjugate+rescale.
    {
        u64 S0 = add2(add2(M[0][0], M[1][0]), add2(M[2][0], M[3][0]));
        u64 S1 = add2(add2(M[0][1], M[1][1]), add2(M[2][1], M[3][1]));
        u64 S2 = add2(add2(M[0][2], M[1][2]), add2(M[2][2], M[3][2]));
        u64 S3 = add2(add2(M[0][3], M[1][3]), add2(M[2][3], M[3][3]));
        adjscale(S0, S1, S2, S3, c0, c1, c2, c3);
    }

    // 18 full iterations, zero MUFU.
    #pragma unroll 1
    for (int it = 0; it < ITERS - 2; it++) {
        u64 T0, T1, T2, T3;
        matvec_row(M, c0, c1, c2, c3, T0, T1, T2, T3);
        adjscale(T0, T1, T2, T3, r0, r1, r2, r3);

        u64 S0, S1, S2, S3;
        matvec_col(M, r0, r1, r2, r3, S0, S1, S2, S3);
        adjscale(S0, S1, S2, S3, c0, c1, c2, c3);
    }

    // Final iteration: row adjugate, then col pass made EXACT via K.
    {
        u64 T0, T1, T2, T3;
        matvec_row(M, c0, c1, c2, c3, T0, T1, T2, T3);
        adjscale(T0, T1, T2, T3, r0, r1, r2, r3);

        u64 S0, S1, S2, S3, K;
        matvec_col(M, r0, r1, r2, r3, S0, S1, S2, S3);
        adjscaleK(S0, S1, S2, S3, c0, c1, c2, c3, K);

        // c_j currently = K/S_j; divide out K so col sums are exactly 1.
        float kl, kh;
        unpack2(K, kl, kh);
        u64 kk = pack2(frcp(kl), frcp(kh));
        c0 = mul2(c0, kk);
        c1 = mul2(c1, kk);
        c2 = mul2(c2, kk);
        c3 = mul2(c3, kk);
    }

    // ---- Epilogue: N_ij = M_ij * c_j * r_i (row scale K_r cancels: it is common
    // to all entries of the matrix only through r, and reference's final op is the
    // col-normalize we just made exact) ----
    u64 rr[4] = {r0, r1, r2, r3};
    u64 cc[4] = {c0, c1, c2, c3};
    #pragma unroll
    for (int i = 0; i < 4; i++) {
        float a0, a1, a2, a3, b0, b1, b2, b3;
        u64 n0 = mul2(mul2(M[i][0], cc[0]), rr[i]);
        u64 n1 = mul2(mul2(M[i][1], cc[1]), rr[i]);
        u64 n2 = mul2(mul2(M[i][2], cc[2]), rr[i]);
        u64 n3 = mul2(mul2(M[i][3], cc[3]), rr[i]);
        unpack2(n0, a0, b0);
        unpack2(n1, a1, b1);
        unpack2(n2, a2, b2);
        unpack2(n3, a3, b3);
        __stcs(oc + (size_t)ta * 4 + i, make_float4(a0, a1, a2, a3));
        if (vb) __stcs(oc + (size_t)tb * 4 + i, make_float4(b0, b1, b2, b3));
    }
}

extern "C" void kernel_launch(void* const* d_in, const int* in_sizes, int n_in,
                              void* d_out, int out_size)
{
    const float* mixes    = (const float*)d_in[0];
    const float* hc_scale = (const float*)d_in[1];
    const float* hc_base  = (const float*)d_in[2];

    const int n_tok  = in_sizes[0] / 24;
    const int n_half = (n_tok + 1) / 2;
    const int block  = 256;
    const int grid   = (n_half + block - 1) / block;

    hc_sinkhorn_kernel<<<grid, block>>>(mixes, hc_scale, hc_base,
                                        (float*)d_out, n_tok, n_half);
}

// round 13
// speedup vs baseline: 1.0714x; 1.0428x over previous
#include <cuda_runtime.h>
#include <cuda_bf16.h>

#define EPS 1e-6f
#define ITERS 20

typedef unsigned long long u64;

__device__ __forceinline__ float frcp(float x) {
    float y;
    asm("rcp.approx.ftz.f32 %0, %1;" : "=f"(y) : "f"(x));
    return y;
}
__device__ __forceinline__ u64 pack2(float lo, float hi) {
    u64 r;
    asm("mov.b64 %0, {%1, %2};" : "=l"(r) : "f"(lo), "f"(hi));
    return r;
}
__device__ __forceinline__ void unpack2(u64 v, float& lo, float& hi) {
    asm("mov.b64 {%0, %1}, %2;" : "=f"(lo), "=f"(hi) : "l"(v));
}
__device__ __forceinline__ u64 mul2(u64 a, u64 b) {
    u64 d;
    asm("mul.rn.f32x2 %0, %1, %2;" : "=l"(d) : "l"(a), "l"(b));
    return d;
}
__device__ __forceinline__ u64 add2(u64 a, u64 b) {
    u64 d;
    asm("add.rn.f32x2 %0, %1, %2;" : "=l"(d) : "l"(a), "l"(b));
    return d;
}
__device__ __forceinline__ u64 fma2(u64 a, u64 b, u64 c) {
    u64 d;
    asm("fma.rn.f32x2 %0, %1, %2, %3;" : "=l"(d) : "l"(a), "l"(b), "l"(c));
    return d;
}

// Per-lane power-of-two ~1/w: s = 2^{-E(w)-1}, so s*w in [0.5, 1). Pure int ALU.
__device__ __forceinline__ u64 pow2rcp(u64 w) {
    unsigned lo = (unsigned)w;
    unsigned hi = (unsigned)(w >> 32);
    lo = 0x7E800000u - (lo & 0x7F800000u);
    hi = 0x7E800000u - (hi & 0x7F800000u);
    return (u64)lo | ((u64)hi << 32);
}

// Adjugate pass with power-of-2 renormalization: r_i = (s*w)/T_i, s*w in [0.5,1).
__device__ __forceinline__ void adjscale(u64 T0, u64 T1, u64 T2, u64 T3,
                                         u64& r0, u64& r1, u64& r2, u64& r3) {
    u64 u = mul2(T0, T1);
    u64 v = mul2(T2, T3);
    u64 w = mul2(u, v);
    u64 s = pow2rcp(w);
    u64 sv = mul2(s, v);
    u64 su = mul2(s, u);
    r0 = mul2(sv, T1);
    r1 = mul2(sv, T0);
    r2 = mul2(su, T3);
    r3 = mul2(su, T2);
}

// Same, but also returns K = s*w (the common normalization constant).
__device__ __forceinline__ void adjscaleK(u64 T0, u64 T1, u64 T2, u64 T3,
                                          u64& r0, u64& r1, u64& r2, u64& r3,
                                          u64& K) {
    u64 u = mul2(T0, T1);
    u64 v = mul2(T2, T3);
    u64 w = mul2(u, v);
    u64 s = pow2rcp(w);
    u64 sv = mul2(s, v);
    u64 su = mul2(s, u);
    K  = mul2(sv, u);
    r0 = mul2(sv, T1);
    r1 = mul2(sv, T0);
    r2 = mul2(su, T3);
    r3 = mul2(su, T2);
}

// Phase 1 helper: pre/post for one token from its first two float4s.
__device__ __forceinline__ void prepost(float4 v0, float4 v1, int t, bool st,
                                        float4* op, float4* oq,
                                        float s0, float s1, const float* sb)
{
    float p[4] = {v0.x, v0.y, v0.z, v0.w};
    #pragma unroll
    for (int i = 0; i < 4; i++)
        p[i] = frcp(1.0f + __expf(-fmaf(p[i], s0, sb[i]))) + EPS;
    if (st) __stcs(op + t, make_float4(p[0], p[1], p[2], p[3]));

    float q[4] = {v1.x, v1.y, v1.z, v1.w};
    #pragma unroll
    for (int i = 0; i < 4; i++)
        q[i] = 2.0f * frcp(1.0f + __expf(-fmaf(q[i], s1, sb[4 + i])));
    if (st) __stcs(oq + t, make_float4(q[0], q[1], q[2], q[3]));
}

// Phase 2/3 helper: comb matrix (softmax rows + EPS) for one token.
__device__ __forceinline__ void combmat(const float* __restrict__ mixes, int t,
                                        float s2, const float* sb, float m[16])
{
    const float4* mp = (const float4*)(mixes + (size_t)t * 24);
    float4 v2 = __ldcs(mp + 2);
    float4 v3 = __ldcs(mp + 3);
    float4 v4 = __ldcs(mp + 4);
    float4 v5 = __ldcs(mp + 5);
    float mm[16] = {v2.x, v2.y, v2.z, v2.w,
                    v3.x, v3.y, v3.z, v3.w,
                    v4.x, v4.y, v4.z, v4.w,
                    v5.x, v5.y, v5.z, v5.w};
    #pragma unroll
    for (int i = 0; i < 4; i++) {
        #pragma unroll
        for (int j = 0; j < 4; j++)
            mm[i * 4 + j] = __expf(fmaf(mm[i * 4 + j], s2, sb[8 + i * 4 + j]));
        float inv = frcp((mm[i * 4] + mm[i * 4 + 1]) + (mm[i * 4 + 2] + mm[i * 4 + 3]));
        #pragma unroll
        for (int j = 0; j < 4; j++)
            m[i * 4 + j] = fmaf(mm[i * 4 + j], inv, EPS);
    }
}

__global__ __launch_bounds__(256, 4)
void hc_sinkhorn_kernel(const float* __restrict__ mixes,
                        const float* __restrict__ hc_scale,
                        const float* __restrict__ hc_base,
                        float* __restrict__ out,
                        int n_tok, int n_half)
{
    __shared__ float sb[24];
    __shared__ float ss[3];
    if (threadIdx.x < 24) sb[threadIdx.x] = hc_base[threadIdx.x];
    if (threadIdx.x < 3)  ss[threadIdx.x] = hc_scale[threadIdx.x];
    __syncthreads();

    const int t = blockIdx.x * blockDim.x + threadIdx.x;
    if (t >= n_half) return;

    const int ta = t;
    const int tb = t + n_half;
    const bool vb = (tb < n_tok);
    const int tbe = vb ? tb : ta;

    const float s0 = ss[0], s1 = ss[1], s2 = ss[2];
    float4* op = (float4*)out;
    float4* oq = (float4*)(out + (size_t)n_tok * 4);

    // ---- Phase 1: pre/post for both tokens (low register footprint) ----
    {
        const float4* mpa = (const float4*)(mixes + (size_t)ta * 24);
        const float4* mpb = (const float4*)(mixes + (size_t)tbe * 24);
        float4 a0 = __ldcs(mpa + 0), a1 = __ldcs(mpa + 1);
        float4 b0 = __ldcs(mpb + 0), b1 = __ldcs(mpb + 1);
        prepost(a0, a1, ta, true, op, oq, s0, s1, sb);
        prepost(b0, b1, tbe, vb, op, oq, s0, s1, sb);
    }

    // ---- Phase 2+3: comb matrices, then pack token-pairs into f32x2 lanes ----
    u64 M[16];
    {
        float ml[16];
        combmat(mixes, ta, s2, sb, ml);
        float mh[16];
        combmat(mixes, tbe, s2, sb, mh);
        #pragma unroll
        for (int k = 0; k < 16; k++)
            M[k] = pack2(ml[k], mh[k]);
    }

    // ---- Sinkhorn, projective: every pass renormalized to K in [0.5,1) ----
    u64 r0, r1, r2, r3, c0, c1, c2, c3;

    {
        u64 S0 = add2(add2(M[0], M[4]), add2(M[8],  M[12]));
        u64 S1 = add2(add2(M[1], M[5]), add2(M[9],  M[13]));
        u64 S2 = add2(add2(M[2], M[6]), add2(M[10], M[14]));
        u64 S3 = add2(add2(M[3], M[7]), add2(M[11], M[15]));
        adjscale(S0, S1, S2, S3, c0, c1, c2, c3);
    }

    #pragma unroll 1
    for (int it = 0; it < ITERS - 2; it++) {
        u64 T0 = mul2(M[0],  c0);
        u64 T1 = mul2(M[4],  c0);
        u64 T2 = mul2(M[8],  c0);
        u64 T3 = mul2(M[12], c0);
        T0 = fma2(M[1],  c1, T0);
        T1 = fma2(M[5],  c1, T1);
        T2 = fma2(M[9],  c1, T2);
        T3 = fma2(M[13], c1, T3);
        T0 = fma2(M[2],  c2, T0);
        T1 = fma2(M[6],  c2, T1);
        T2 = fma2(M[10], c2, T2);
        T3 = fma2(M[14], c2, T3);
        T0 = fma2(M[3],  c3, T0);
        T1 = fma2(M[7],  c3, T1);
        T2 = fma2(M[11], c3, T2);
        T3 = fma2(M[15], c3, T3);
        adjscale(T0, T1, T2, T3, r0, r1, r2, r3);

        u64 S0 = mul2(M[0], r0);
        u64 S1 = mul2(M[1], r0);
        u64 S2 = mul2(M[2], r0);
        u64 S3 = mul2(M[3], r0);
        S0 = fma2(M[4],  r1, S0);
        S1 = fma2(M[5],  r1, S1);
        S2 = fma2(M[6],  r1, S2);
        S3 = fma2(M[7],  r1, S3);
        S0 = fma2(M[8],  r2, S0);
        S1 = fma2(M[9],  r2, S1);
        S2 = fma2(M[10], r2, S2);
        S3 = fma2(M[11], r2, S3);
        S0 = fma2(M[12], r3, S0);
        S1 = fma2(M[13], r3, S1);
        S2 = fma2(M[14], r3, S2);
        S3 = fma2(M[15], r3, S3);
        adjscale(S0, S1, S2, S3, c0, c1, c2, c3);
    }

    // Final iteration: row adjugate, then EXACT col normalize via K.
    {
        u64 T0 = mul2(M[0],  c0);
        u64 T1 = mul2(M[4],  c0);
        u64 T2 = mul2(M[8],  c0);
        u64 T3 = mul2(M[12], c0);
        T0 = fma2(M[1],  c1, T0);
        T1 = fma2(M[5],  c1, T1);
        T2 = fma2(M[9],  c1, T2);
        T3 = fma2(M[13], c1, T3);
        T0 = fma2(M[2],  c2, T0);
        T1 = fma2(M[6],  c2, T1);
        T2 = fma2(M[10], c2, T2);
        T3 = fma2(M[14], c2, T3);
        T0 = fma2(M[3],  c3, T0);
        T1 = fma2(M[7],  c3, T1);
        T2 = fma2(M[11], c3, T2);
        T3 = fma2(M[15], c3, T3);
        adjscale(T0, T1, T2, T3, r0, r1, r2, r3);

        u64 S0 = mul2(M[0], r0);
        u64 S1 = mul2(M[1], r0);
        u64 S2 = mul2(M[2], r0);
        u64 S3 = mul2(M[3], r0);
        S0 = fma2(M[4],  r1, S0);
        S1 = fma2(M[5],  r1, S1);
        S2 = fma2(M[6],  r1, S2);
        S3 = fma2(M[7],  r1, S3);
        S0 = fma2(M[8],  r2, S0);
        S1 = fma2(M[9],  r2, S1);
        S2 = fma2(M[10], r2, S2);
        S3 = fma2(M[11], r2, S3);
        S0 = fma2(M[12], r3, S0);
        S1 = fma2(M[13], r3, S1);
        S2 = fma2(M[14], r3, S2);
        S3 = fma2(M[15], r3, S3);
        u64 K;
        adjscaleK(S0, S1, S2, S3, c0, c1, c2, c3, K);

        float kl, kh;
        unpack2(K, kl, kh);
        u64 kk = pack2(frcp(kl), frcp(kh));
        c0 = mul2(c0, kk);
        c1 = mul2(c1, kk);
        c2 = mul2(c2, kk);
        c3 = mul2(c3, kk);
    }

    // ---- Epilogue: N_ij = M_ij * c_j * r_i ----
    float4* oc = (float4*)(out + (size_t)n_tok * 8);
    u64 rr[4] = {r0, r1, r2, r3};
    u64 cc[4] = {c0, c1, c2, c3};
    #pragma unroll
    for (int i = 0; i < 4; i++) {
        float a0, a1, a2, a3, b0, b1, b2, b3;
        u64 n0 = mul2(mul2(M[i * 4 + 0], cc[0]), rr[i]);
        u64 n1 = mul2(mul2(M[i * 4 + 1], cc[1]), rr[i]);
        u64 n2 = mul2(mul2(M[i * 4 + 2], cc[2]), rr[i]);
        u64 n3 = mul2(mul2(M[i * 4 + 3], cc[3]), rr[i]);
        unpack2(n0, a0, b0);
        unpack2(n1, a1, b1);
        unpack2(n2, a2, b2);
        unpack2(n3, a3, b3);
        __stcs(oc + (size_t)ta * 4 + i, make_float4(a0, a1, a2, a3));
        if (vb) __stcs(oc + (size_t)tb * 4 + i, make_float4(b0, b1, b2, b3));
    }
}

extern "C" void kernel_launch(void* const* d_in, const int* in_sizes, int n_in,
                              void* d_out, int out_size)
{
    const float* mixes    = (const float*)d_in[0];
    const float* hc_scale = (const float*)d_in[1];
    const float* hc_base  = (const float*)d_in[2];

    const int n_tok  = in_sizes[0] / 24;
    const int n_half = (n_tok + 1) / 2;
    const int block  = 256;
    const int grid   = (n_half + block - 1) / block;

    hc_sinkhorn_kernel<<<grid, block>>>(mixes, hc_scale, hc_base,
                                        (float*)d_out, n_tok, n_half);
}